// round 8
// baseline (speedup 1.0000x reference)
#include <cuda_runtime.h>
#include <math.h>

#define NN 4096
#define NF 4096
#define NH 4
#define NO 8
#define NC32 32            // NH*NO
#define NW (NN/32)         // bitmask words per row = 128
#define JS 32              // j-splits for attention (grid.y)
#define KS 16              // k-splits for gemm
#define GAT_ALPHA 0.2f
#define L2E 1.44269504088896341f
#define KA  0.28853900817792683f   // 0.2 * log2(e)

// ---------------- scratch (__device__ globals; no allocations) ----------------
__device__ float         g_Cpart[KS][NN * NC32];  // k-split GEMM partials (8MB)
__device__ float         g_Wh[NN * NC32];         // Wh[j][h*8+o]  (512KB, L2-resident)
__device__ float         g_sdst4[NN * NH];        // s_dst[j][h]
__device__ float         g_ssrc4[NN * NH];        // s_src[i][h]
__device__ unsigned      g_bmT[NW * NN];          // bitmask, transposed: [jw][i] (2MB)
__device__ unsigned      g_maxsd[NH];             // global max of s_dst per head (keyed)
__device__ float         g_hp[NN * NC32];         // atomically accumulated h' numer (1MB)
__device__ float         g_z[NN * NH];            // atomically accumulated Z
__device__ float         g_ls[NN * NO];           // log_softmax(node_embeddings)

// ---------------- helpers ----------------
__device__ __forceinline__ void ffma2(unsigned long long& d, unsigned long long a,
                                      unsigned long long b) {
    asm("fma.rn.f32x2 %0, %1, %2, %0;" : "+l"(d) : "l"(a), "l"(b));
}
__device__ __forceinline__ void addf2(unsigned long long& d, unsigned long long a) {
    asm("add.rn.f32x2 %0, %0, %1;" : "+l"(d) : "l"(a));
}
__device__ __forceinline__ unsigned long long packab(float a, float b) {
    unsigned long long r;
    asm("mov.b64 %0, {%1, %2};" : "=l"(r) : "f"(a), "f"(b));
    return r;
}
__device__ __forceinline__ float ex2f(float x) {
    float r;
    asm("ex2.approx.ftz.f32 %0, %1;" : "=f"(r) : "f"(x));
    return r;
}
union U64F2 { unsigned long long u; float2 f; };

// monotonic float<->uint key for atomicMax over signed floats
__device__ __forceinline__ unsigned fkey(float f) {
    unsigned u = __float_as_uint(f);
    return (u & 0x80000000u) ? ~u : (u | 0x80000000u);
}
__device__ __forceinline__ float funkey(unsigned k) {
    return __uint_as_float((k & 0x80000000u) ? (k & 0x7FFFFFFFu) : ~k);
}

// ---------------- 1) pack adjacency; reset maxsd; zero atomic outputs ----------------
__global__ void k_pack(const int* __restrict__ adj) {
    int gt = blockIdx.x * 256 + threadIdx.x;          // 512*256 = NN*NC32
    g_hp[gt] = 0.f;
    if (gt < NN * NH) g_z[gt] = 0.f;
    if (gt < NH) g_maxsd[gt] = 0u;

    int w = threadIdx.x >> 5, lane = threadIdx.x & 31;
    int i = blockIdx.x * 8 + w;
    const int* row = adj + (size_t)i * NN;
#pragma unroll 4
    for (int jw = 0; jw < NW; jw++) {
        int v = __ldg(row + jw * 32 + lane);
        unsigned word = __ballot_sync(0xffffffffu, v != 0);
        if (lane == 0) g_bmT[jw * NN + i] = word;
    }
}

// ---------------- 2) Wh = x @ Wc  (k-split x16, BM=64, f32x2 inner) ----------------
__global__ void k_gemm(const float* __restrict__ x, const float* __restrict__ W) {
    __shared__ float xs[64][40];
    __shared__ float ws[32][36];
    int t = threadIdx.x;
    int c = t & 31, rg = t >> 5;
    int row0 = blockIdx.x * 64;
    int kbase = blockIdx.y * (NF / KS);
    unsigned long long acc2a[8], acc2b[8];
#pragma unroll
    for (int r = 0; r < 8; r++) { acc2a[r] = 0ull; acc2b[r] = 0ull; }

    for (int kt = 0; kt < NF / KS; kt += 32) {
        int k0 = kbase + kt;
#pragma unroll
        for (int q = 0; q < 2; q++) {
            int s = t * 2 + q;
            int r = s >> 3, kq = s & 7;
            float4 v = __ldg((const float4*)(x + (size_t)(row0 + r) * NF + k0 + kq * 4));
            *(float4*)&xs[r][kq * 4] = v;
        }
        {
            int k = t >> 3, c4 = (t & 7) * 4;
            int h = c4 >> 3, o = c4 & 7;
            float4 v = __ldg((const float4*)(W + (size_t)h * NF * NO + (size_t)(k0 + k) * NO + o));
            *(float4*)&ws[k][c4] = v;
        }
        __syncthreads();
#pragma unroll
        for (int k4 = 0; k4 < 32; k4 += 4) {
            unsigned long long wp0 = packab(ws[k4][c],     ws[k4 + 1][c]);
            unsigned long long wp1 = packab(ws[k4 + 2][c], ws[k4 + 3][c]);
#pragma unroll
            for (int r = 0; r < 8; r++) {
                ulonglong2 xv = *(const ulonglong2*)&xs[rg * 8 + r][k4];
                ffma2(acc2a[r], xv.x, wp0);
                ffma2(acc2b[r], xv.y, wp1);
            }
        }
        __syncthreads();
    }
    float* outp = g_Cpart[blockIdx.y];
#pragma unroll
    for (int r = 0; r < 8; r++) {
        U64F2 a, b; a.u = acc2a[r]; b.u = acc2b[r];
        outp[(size_t)(row0 + rg * 8 + r) * NC32 + c] = (a.f.x + a.f.y) + (b.f.x + b.f.y);
    }
}

// ---------------- 3) reduce k-split partials; s_src/s_dst; global sd max ----------------
__global__ void k_whfin(const float* __restrict__ a) {
    int i = blockIdx.x * blockDim.x + threadIdx.x;   // one row per thread
    int lane = threadIdx.x & 31, w = threadIdx.x >> 5;
    float v[32];
#pragma unroll
    for (int c4 = 0; c4 < 8; c4++) {
        float4 s = make_float4(0.f, 0.f, 0.f, 0.f);
#pragma unroll
        for (int ks = 0; ks < KS; ks++) {
            float4 p = *(const float4*)&g_Cpart[ks][(size_t)i * NC32 + c4 * 4];
            s.x += p.x; s.y += p.y; s.z += p.z; s.w += p.w;
        }
        v[c4 * 4 + 0] = s.x; v[c4 * 4 + 1] = s.y; v[c4 * 4 + 2] = s.z; v[c4 * 4 + 3] = s.w;
        *(float4*)&g_Wh[(size_t)i * NC32 + c4 * 4] = s;
    }
    float sdv[NH];
#pragma unroll
    for (int h = 0; h < NH; h++) {
        float ss = 0.f, sd = 0.f;
#pragma unroll
        for (int o = 0; o < NO; o++) {
            float wv = v[h * 8 + o];
            ss = fmaf(wv, __ldg(a + h * 16 + o), ss);
            sd = fmaf(wv, __ldg(a + h * 16 + 8 + o), sd);
        }
        g_ssrc4[i * NH + h] = ss;
        g_sdst4[i * NH + h] = sd;
        sdv[h] = sd;
    }
    __shared__ float mred[NH][8];
#pragma unroll
    for (int h = 0; h < NH; h++) {
        float m = sdv[h];
#pragma unroll
        for (int off = 16; off > 0; off >>= 1)
            m = fmaxf(m, __shfl_xor_sync(0xffffffffu, m, off));
        if (lane == 0) mred[h][w] = m;
    }
    __syncthreads();
    if (threadIdx.x < NH) {
        int h = threadIdx.x;
        float m = mred[h][0];
#pragma unroll
        for (int ww = 1; ww < 8; ww++) m = fmaxf(m, mred[h][ww]);
        atomicMax(&g_maxsd[h], fkey(m));
    }
}

// ---------------- 4) main attention pass: factored exp, smem j-tiles ----------------
// grid (NN/128, JS), block 128.  Warp w owns i = bx*128 + w*32 + lane.
// Block covers NW/JS = 4 words = 128 j, staged in 2 chunks of 64.
// wt = adj ? ((sd>=-ss) ? A_i*B_j : C_i*D_j) : 0    (lrelu piecewise factorization)
__global__ void __launch_bounds__(128, 6) k_attn() {
    __shared__ float s_wh[64 * 32];   // 8KB: Wh for 64 j, head-pair interleaved
    __shared__ float s_bd[64 * 8];    // 2KB: (B,D) per head per j
    int lane = threadIdx.x & 31, w = threadIdx.x >> 5;
    int i = blockIdx.x * 128 + w * 32 + lane;
    int jw0 = blockIdx.y * (NW / JS);

    float A[4], C[4], Bth[4];
#pragma unroll
    for (int h = 0; h < 4; h++) {
        float ss = g_ssrc4[i * 4 + h];
        float M = funkey(g_maxsd[h]);      // global upper bound of sd (lrelu monotone)
        float e = ss + M;
        e = fmaxf(e, GAT_ALPHA * e);
        float ml = e * L2E;
        A[h]   = ex2f(fmaf(ss,  L2E, -ml));
        C[h]   = ex2f(fmaf(ss,  KA,  -ml));
        Bth[h] = ex2f(-L2E * ss);          // B_j >= Bth  <=>  sd_j >= -ss
    }

    unsigned long long acc01[8], acc23[8], Zp0 = 0ull, Zp1 = 0ull;
#pragma unroll
    for (int q = 0; q < 8; q++) { acc01[q] = 0ull; acc23[q] = 0ull; }

    for (int ch = 0; ch < 2; ch++) {                   // 2 chunks of 64 j
        int jwc = jw0 + ch * 2;
        int j0 = jwc * 32;
        __syncthreads();                                // protect previous chunk
        // stage Wh head-pair interleaved: s_wh[j*32 + (h>>1)*16 + o*2 + (h&1)]
#pragma unroll
        for (int q = 0; q < 4; q++) {
            int f = q * 128 + threadIdx.x;              // 0..511 float4s
            int j = f >> 3, c4 = (f & 7) * 4;
            float4 v = *(const float4*)(g_Wh + (size_t)(j0 + j) * 32 + c4);
            int h = c4 >> 3, o0 = c4 & 7;
            float* dst = &s_wh[j * 32 + (h >> 1) * 16 + (h & 1)];
            dst[(o0 + 0) * 2] = v.x;
            dst[(o0 + 1) * 2] = v.y;
            dst[(o0 + 2) * 2] = v.z;
            dst[(o0 + 3) * 2] = v.w;
        }
        if (threadIdx.x < 64) {
            float4 sd = ((const float4*)g_sdst4)[j0 + threadIdx.x];
            float* bd = &s_bd[threadIdx.x * 8];
            bd[0] = ex2f(L2E * sd.x); bd[1] = ex2f(KA * sd.x);
            bd[2] = ex2f(L2E * sd.y); bd[3] = ex2f(KA * sd.y);
            bd[4] = ex2f(L2E * sd.z); bd[5] = ex2f(KA * sd.z);
            bd[6] = ex2f(L2E * sd.w); bd[7] = ex2f(KA * sd.w);
        }
        __syncthreads();
#pragma unroll
        for (int wseg = 0; wseg < 2; wseg++) {
            unsigned word = g_bmT[(jwc + wseg) * NN + i];
            int jbase = wseg * 32;
#pragma unroll 8
            for (int b = 0; b < 32; b++) {
                int jj = jbase + b;
                bool on = (word >> b) & 1u;
                float4 bd01 = *(const float4*)&s_bd[jj * 8];      // B0 D0 B1 D1
                float4 bd23 = *(const float4*)&s_bd[jj * 8 + 4];  // B2 D2 B3 D3
                bool p0 = bd01.x >= Bth[0];
                bool p1 = bd01.z >= Bth[1];
                bool p2 = bd23.x >= Bth[2];
                bool p3 = bd23.z >= Bth[3];
                float wt0 = (p0 ? A[0] : C[0]) * (p0 ? bd01.x : bd01.y);
                float wt1 = (p1 ? A[1] : C[1]) * (p1 ? bd01.z : bd01.w);
                float wt2 = (p2 ? A[2] : C[2]) * (p2 ? bd23.x : bd23.y);
                float wt3 = (p3 ? A[3] : C[3]) * (p3 ? bd23.z : bd23.w);
                wt0 = on ? wt0 : 0.f;
                wt1 = on ? wt1 : 0.f;
                wt2 = on ? wt2 : 0.f;
                wt3 = on ? wt3 : 0.f;
                unsigned long long w01 = packab(wt0, wt1);
                unsigned long long w23 = packab(wt2, wt3);
                addf2(Zp0, w01);
                addf2(Zp1, w23);
                const ulonglong2* wp = (const ulonglong2*)&s_wh[jj * 32];
                ulonglong2 q0 = wp[0], q1 = wp[1], q2 = wp[2], q3 = wp[3];
                ffma2(acc01[0], w01, q0.x); ffma2(acc01[1], w01, q0.y);
                ffma2(acc01[2], w01, q1.x); ffma2(acc01[3], w01, q1.y);
                ffma2(acc01[4], w01, q2.x); ffma2(acc01[5], w01, q2.y);
                ffma2(acc01[6], w01, q3.x); ffma2(acc01[7], w01, q3.y);
                ulonglong2 r0 = wp[4], r1 = wp[5], r2 = wp[6], r3 = wp[7];
                ffma2(acc23[0], w23, r0.x); ffma2(acc23[1], w23, r0.y);
                ffma2(acc23[2], w23, r1.x); ffma2(acc23[3], w23, r1.y);
                ffma2(acc23[4], w23, r2.x); ffma2(acc23[5], w23, r2.y);
                ffma2(acc23[6], w23, r3.x); ffma2(acc23[7], w23, r3.y);
            }
        }
    }

    // per-lane direct atomic accumulation (warps own disjoint i)
    float* hp = g_hp + (size_t)i * NC32;
#pragma unroll
    for (int o = 0; o < 8; o++) {
        U64F2 c01; c01.u = acc01[o];
        atomicAdd(&hp[0 * 8 + o], c01.f.x);
        atomicAdd(&hp[1 * 8 + o], c01.f.y);
        U64F2 c23; c23.u = acc23[o];
        atomicAdd(&hp[2 * 8 + o], c23.f.x);
        atomicAdd(&hp[3 * 8 + o], c23.f.y);
    }
    U64F2 z01, z23; z01.u = Zp0; z23.u = Zp1;
    atomicAdd(&g_z[i * 4 + 0], z01.f.x);
    atomicAdd(&g_z[i * 4 + 1], z01.f.y);
    atomicAdd(&g_z[i * 4 + 2], z23.f.x);
    atomicAdd(&g_z[i * 4 + 3], z23.f.y);
}

// ---------------- 5) normalize, mean over heads, log_softmax; seed bias ----------------
__global__ void k_fin1(float* __restrict__ dne, int write_ne,
                       float* __restrict__ dout, int write_out,
                       const float* __restrict__ bl) {
    int i = blockIdx.x * 64 + threadIdx.x;    // grid 64, block 64
    if (blockIdx.x == 0 && threadIdx.x < 8 && write_out)
        dout[threadIdx.x] = __ldg(bl);        // seed bias for k_fin2 atomics
    float4 z4 = *(const float4*)&g_z[i * 4];
    float zi[4] = { 0.25f / fmaxf(z4.x, 1e-30f), 0.25f / fmaxf(z4.y, 1e-30f),
                    0.25f / fmaxf(z4.z, 1e-30f), 0.25f / fmaxf(z4.w, 1e-30f) };
    float ne[8];
#pragma unroll
    for (int o = 0; o < 8; o++) ne[o] = 0.f;
#pragma unroll
    for (int h = 0; h < 4; h++) {
        float4 p0 = *(const float4*)&g_hp[(size_t)i * NC32 + h * 8];
        float4 p1 = *(const float4*)&g_hp[(size_t)i * NC32 + h * 8 + 4];
        ne[0] = fmaf(p0.x, zi[h], ne[0]); ne[1] = fmaf(p0.y, zi[h], ne[1]);
        ne[2] = fmaf(p0.z, zi[h], ne[2]); ne[3] = fmaf(p0.w, zi[h], ne[3]);
        ne[4] = fmaf(p1.x, zi[h], ne[4]); ne[5] = fmaf(p1.y, zi[h], ne[5]);
        ne[6] = fmaf(p1.z, zi[h], ne[6]); ne[7] = fmaf(p1.w, zi[h], ne[7]);
    }
    float m = ne[0];
#pragma unroll
    for (int o = 1; o < 8; o++) m = fmaxf(m, ne[o]);
    float sum = 0.f;
#pragma unroll
    for (int o = 0; o < 8; o++) sum += expf(ne[o] - m);
    float lse = logf(sum) + m;
#pragma unroll
    for (int o = 0; o < 8; o++) g_ls[(size_t)i * NO + o] = ne[o] - lse;
    if (write_ne) {
#pragma unroll
        for (int o = 0; o < 8; o++) dne[(size_t)i * NO + o] = ne[o];
    }
}

// ---------------- 6) out = ls.T @ w_lin.T + b  (8 blocks, atomic finish) ----------------
__global__ void k_fin2(const float* __restrict__ wl, float* __restrict__ dout,
                       int write_out) {
    __shared__ float rb[256][8];
    int t = threadIdx.x;
    int i0 = blockIdx.x * 512;
    float p[8];
#pragma unroll
    for (int o = 0; o < 8; o++) p[o] = 0.f;
#pragma unroll
    for (int q = 0; q < 2; q++) {
        int i = i0 + q * 256 + t;
        float wv = __ldg(wl + i);
        float4 l0 = *(const float4*)&g_ls[(size_t)i * NO];
        float4 l1 = *(const float4*)&g_ls[(size_t)i * NO + 4];
        p[0] = fmaf(l0.x, wv, p[0]); p[1] = fmaf(l0.y, wv, p[1]);
        p[2] = fmaf(l0.z, wv, p[2]); p[3] = fmaf(l0.w, wv, p[3]);
        p[4] = fmaf(l1.x, wv, p[4]); p[5] = fmaf(l1.y, wv, p[5]);
        p[6] = fmaf(l1.z, wv, p[6]); p[7] = fmaf(l1.w, wv, p[7]);
    }
#pragma unroll
    for (int o = 0; o < 8; o++) rb[t][o] = p[o];
    __syncthreads();
    if (t < 8 && write_out) {
        float s = 0.f;
        for (int q = 0; q < 256; q++) s += rb[q][t];
        atomicAdd(&dout[t], s);
    }
}

// ---------------- launch ----------------
extern "C" void kernel_launch(void* const* d_in, const int* in_sizes, int n_in,
                              void* d_out, int out_size) {
    const float* x   = (const float*)d_in[0];
    const int*   adj = (const int*)d_in[1];
    const float* W   = (const float*)d_in[2];
    const float* a   = (const float*)d_in[3];
    const float* wl  = (const float*)d_in[4];
    const float* bl  = (const float*)d_in[5];
    float* outp = (float*)d_out;

    int write_out = 0, write_ne = 0, ne_off = 0;
    if (out_size >= 8 + NN * NO)      { write_out = 1; write_ne = 1; ne_off = 8; }
    else if (out_size == NN * NO)     { write_ne = 1; ne_off = 0; }
    else                              { write_out = 1; }

    k_pack<<<NN / 8, 256>>>(adj);
    dim3 gg(NN / 64, KS);
    k_gemm<<<gg, 256>>>(x, W);
    k_whfin<<<NN / 256, 256>>>(a);
    dim3 ga(NN / 128, JS);
    k_attn<<<ga, 128>>>();
    k_fin1<<<NN / 64, 64>>>(outp + ne_off, write_ne, outp, write_out, bl);
    k_fin2<<<8, 256>>>(wl, outp, write_out);
}

// round 9
// speedup vs baseline: 1.4697x; 1.4697x over previous
#include <cuda_runtime.h>
#include <math.h>

#define NN 4096
#define NF 4096
#define NH 4
#define NO 8
#define NC32 32            // NH*NO
#define NW (NN/32)         // bitmask words per row = 128
#define JS 64              // attention j-splits (grid.y): 64 j per block
#define GKS 32             // k-splits for gemm
#define GAT_ALPHA 0.2f
#define L2E 1.44269504088896341f
#define KA  0.28853900817792683f   // 0.2 * log2(e)

// ---------------- scratch (__device__ globals; no allocations) ----------------
__device__ float         g_Cpart[GKS][NN * NC32]; // k-split GEMM partials (16MB)
__device__ float         g_Wh[NN * NC32];         // Wh interleaved: [i*32 + hp*16 + o*2 + (h&1)]
__device__ float         g_sdst4[NN * NH];        // s_dst[j][h]
__device__ float         g_ssrc4[NN * NH];        // s_src[i][h]
__device__ unsigned      g_bmT[NW * NN];          // bitmask: word g*4+q, bit l <-> j=g*128+4l+q
__device__ unsigned      g_maxsd[NH];             // global max of s_dst per head (keyed)
__device__ float         g_hp[NN * NC32];         // red-accumulated h' numerator (1MB)
__device__ float         g_z[NN * NH];            // red-accumulated Z
__device__ float         g_ls[NN * NO];           // log_softmax(node_embeddings)

// ---------------- helpers ----------------
__device__ __forceinline__ void ffma2(unsigned long long& d, unsigned long long a,
                                      unsigned long long b) {
    asm("fma.rn.f32x2 %0, %1, %2, %0;" : "+l"(d) : "l"(a), "l"(b));
}
__device__ __forceinline__ void addf2(unsigned long long& d, unsigned long long a) {
    asm("add.rn.f32x2 %0, %0, %1;" : "+l"(d) : "l"(a));
}
__device__ __forceinline__ unsigned long long packab(float a, float b) {
    unsigned long long r;
    asm("mov.b64 %0, {%1, %2};" : "=l"(r) : "f"(a), "f"(b));
    return r;
}
__device__ __forceinline__ unsigned long long pack2(float v) {
    unsigned long long r;
    asm("mov.b64 %0, {%1, %1};" : "=l"(r) : "f"(v));
    return r;
}
__device__ __forceinline__ float ex2f(float x) {
    float r;
    asm("ex2.approx.ftz.f32 %0, %1;" : "=f"(r) : "f"(x));
    return r;
}
__device__ __forceinline__ void red4(float* p, float a, float b, float c, float d) {
    asm volatile("red.global.add.v4.f32 [%0], {%1, %2, %3, %4};"
                 :: "l"(p), "f"(a), "f"(b), "f"(c), "f"(d) : "memory");
}
union U64F2 { unsigned long long u; float2 f; };

__device__ __forceinline__ unsigned fkey(float f) {
    unsigned u = __float_as_uint(f);
    return (u & 0x80000000u) ? ~u : (u | 0x80000000u);
}
__device__ __forceinline__ float funkey(unsigned k) {
    return __uint_as_float((k & 0x80000000u) ? (k & 0x7FFFFFFFu) : ~k);
}

// ---------------- 1) pack adjacency (int4 + 4 ballots, permuted bits) ----------------
// word w' = g*4+q, bit l  <->  adj[i][g*128 + l*4 + q]
__global__ void k_pack(const int* __restrict__ adj) {
    int gt = blockIdx.x * 256 + threadIdx.x;          // 512*256 = NN*NC32
    g_hp[gt] = 0.f;
    if (gt < NN * NH) g_z[gt] = 0.f;
    if (gt < NH) g_maxsd[gt] = 0u;

    int w = threadIdx.x >> 5, lane = threadIdx.x & 31;
    int i = blockIdx.x * 8 + w;
    const int4* row = (const int4*)(adj + (size_t)i * NN);
#pragma unroll 4
    for (int g = 0; g < 32; g++) {                    // 32 groups of 128 j
        int4 v = __ldg(row + g * 32 + lane);          // j = g*128 + lane*4 + {0..3}
        unsigned b0 = __ballot_sync(0xffffffffu, v.x != 0);
        unsigned b1 = __ballot_sync(0xffffffffu, v.y != 0);
        unsigned b2 = __ballot_sync(0xffffffffu, v.z != 0);
        unsigned b3 = __ballot_sync(0xffffffffu, v.w != 0);
        if (lane == 0) {
            g_bmT[(size_t)(g * 4 + 0) * NN + i] = b0;
            g_bmT[(size_t)(g * 4 + 1) * NN + i] = b1;
            g_bmT[(size_t)(g * 4 + 2) * NN + i] = b2;
            g_bmT[(size_t)(g * 4 + 3) * NN + i] = b3;
        }
    }
}

// ---------------- 2) Wh = x @ Wc  (BM=256, 8x4 per thread, k-split x32) ----------------
__global__ void __launch_bounds__(256, 3) k_gemm(const float* __restrict__ x,
                                                 const float* __restrict__ W) {
    __shared__ float xs[256 * 36];
    __shared__ float ws[32][36];
    int t = threadIdx.x;
    int c4g = t & 7;           // 4-col group (cols c4g*4..+3)
    int rg = t >> 3;           // 8-row group (rows rg*8..+7)
    int row0 = blockIdx.x * 256;
    int kbase = blockIdx.y * (NF / GKS);   // 128 k per block

    unsigned long long acc01[8], acc23[8];
#pragma unroll
    for (int r = 0; r < 8; r++) { acc01[r] = 0ull; acc23[r] = 0ull; }

    for (int kt = 0; kt < NF / GKS; kt += 32) {
        int k0 = kbase + kt;
#pragma unroll
        for (int q = 0; q < 8; q++) {
            int f = q * 256 + t;
            int row = f >> 3, kq = f & 7;
            float4 v = __ldg((const float4*)(x + (size_t)(row0 + row) * NF + k0 + kq * 4));
            *(float4*)&xs[row * 36 + kq * 4] = v;
        }
        {
            int k = t >> 3, c4 = (t & 7) * 4;
            int h = c4 >> 3, o = c4 & 7;
            float4 v = __ldg((const float4*)(W + (size_t)h * NF * NO + (size_t)(k0 + k) * NO + o));
            *(float4*)&ws[k][c4] = v;
        }
        __syncthreads();
#pragma unroll
        for (int kk = 0; kk < 8; kk++) {
            float4 w0 = *(const float4*)&ws[kk * 4 + 0][c4g * 4];
            float4 w1 = *(const float4*)&ws[kk * 4 + 1][c4g * 4];
            float4 w2 = *(const float4*)&ws[kk * 4 + 2][c4g * 4];
            float4 w3 = *(const float4*)&ws[kk * 4 + 3][c4g * 4];
            unsigned long long w01_0 = packab(w0.x, w0.y), w23_0 = packab(w0.z, w0.w);
            unsigned long long w01_1 = packab(w1.x, w1.y), w23_1 = packab(w1.z, w1.w);
            unsigned long long w01_2 = packab(w2.x, w2.y), w23_2 = packab(w2.z, w2.w);
            unsigned long long w01_3 = packab(w3.x, w3.y), w23_3 = packab(w3.z, w3.w);
#pragma unroll
            for (int r = 0; r < 8; r++) {
                float4 xv = *(const float4*)&xs[(rg * 8 + r) * 36 + kk * 4];
                unsigned long long a0 = pack2(xv.x), a1 = pack2(xv.y);
                unsigned long long a2 = pack2(xv.z), a3 = pack2(xv.w);
                ffma2(acc01[r], a0, w01_0); ffma2(acc23[r], a0, w23_0);
                ffma2(acc01[r], a1, w01_1); ffma2(acc23[r], a1, w23_1);
                ffma2(acc01[r], a2, w01_2); ffma2(acc23[r], a2, w23_2);
                ffma2(acc01[r], a3, w01_3); ffma2(acc23[r], a3, w23_3);
            }
        }
        __syncthreads();
    }
    float* outp = g_Cpart[blockIdx.y];
#pragma unroll
    for (int r = 0; r < 8; r++) {
        U64F2 a, b; a.u = acc01[r]; b.u = acc23[r];
        *(float4*)&outp[(size_t)(row0 + rg * 8 + r) * NC32 + c4g * 4] =
            make_float4(a.f.x, a.f.y, b.f.x, b.f.y);
    }
}

// ---------------- 3) reduce k-splits; interleaved Wh; s_src/s_dst; sd max ----------------
__global__ void k_whfin(const float* __restrict__ av) {
    __shared__ float sm[32][36];
    int t = threadIdx.x;
    int rl = t >> 3;          // local row 0..31
    int c4 = t & 7;           // float4 column group
    int i = blockIdx.x * 32 + rl;

    float4 s = make_float4(0.f, 0.f, 0.f, 0.f);
#pragma unroll
    for (int ks = 0; ks < GKS; ks++) {
        float4 p = *(const float4*)&g_Cpart[ks][(size_t)i * NC32 + c4 * 4];
        s.x += p.x; s.y += p.y; s.z += p.z; s.w += p.w;
    }
    *(float4*)&sm[rl][c4 * 4] = s;
    __syncthreads();

    // interleaved Wh write: dst[i*32 + hp*16 + k4*4] = (v[hp16+2k4], v[hp16+8+2k4], v[hp16+2k4+1], v[hp16+8+2k4+1])
    {
        int hp = c4 >> 2, k4 = c4 & 3;
        float4 o;
        o.x = sm[rl][hp * 16 + 2 * k4];
        o.y = sm[rl][hp * 16 + 8 + 2 * k4];
        o.z = sm[rl][hp * 16 + 2 * k4 + 1];
        o.w = sm[rl][hp * 16 + 8 + 2 * k4 + 1];
        *(float4*)&g_Wh[(size_t)i * NC32 + hp * 16 + k4 * 4] = o;
    }

    if (t < 32) {
        int ii = blockIdx.x * 32 + t;
        float ssv[4], sdv[4];
#pragma unroll
        for (int h = 0; h < NH; h++) {
            float ss = 0.f, sd = 0.f;
#pragma unroll
            for (int o = 0; o < NO; o++) {
                float wv = sm[t][h * 8 + o];
                ss = fmaf(wv, __ldg(av + h * 16 + o), ss);
                sd = fmaf(wv, __ldg(av + h * 16 + 8 + o), sd);
            }
            ssv[h] = ss; sdv[h] = sd;
        }
        *(float4*)&g_ssrc4[ii * 4] = make_float4(ssv[0], ssv[1], ssv[2], ssv[3]);
        *(float4*)&g_sdst4[ii * 4] = make_float4(sdv[0], sdv[1], sdv[2], sdv[3]);
        float m[4] = { sdv[0], sdv[1], sdv[2], sdv[3] };
#pragma unroll
        for (int off = 16; off > 0; off >>= 1) {
#pragma unroll
            for (int h = 0; h < 4; h++)
                m[h] = fmaxf(m[h], __shfl_xor_sync(0xffffffffu, m[h], off));
        }
        if (t == 0) {
#pragma unroll
            for (int h = 0; h < 4; h++) atomicMax(&g_maxsd[h], fkey(m[h]));
        }
    }
}

// ---------------- 4) attention: 64 i per warp, 2 passes over head pairs ----------------
// grid (NN/256, JS=64), block 128.  Lane owns ia and ib=ia+32.
// Block's 64 j = group g = by>>1, l-half (by&1): j = g*128 + l*4 + q, l in [lh, lh+16)
__global__ void __launch_bounds__(128, 4) k_attn() {
    __shared__ float s_wh[64 * 16];   // 4KB: pass head-pair Wh, [j][o*2+e]
    __shared__ float s_sd[64 * 4];    // 1KB: (sdl0, sdk0, sdl1, sdk1) per j
    int lane = threadIdx.x & 31, w = threadIdx.x >> 5;
    int ia = blockIdx.x * 256 + w * 64 + lane;
    int ib = ia + 32;
    int g = blockIdx.y >> 1;
    int lhalf = (blockIdx.y & 1) * 16;
    int j0 = g * 128 + (blockIdx.y & 1) * 64;

    float sslA[4], sskA[4], sslB[4], sskB[4];
#pragma unroll
    for (int h = 0; h < 4; h++) {
        float M = funkey(g_maxsd[h]);      // global upper bound of sd (lrelu monotone)
        float ssa = g_ssrc4[ia * 4 + h];
        float ea = ssa + M; ea = fmaxf(ea, GAT_ALPHA * ea);
        float mla = ea * L2E;
        sslA[h] = fmaf(ssa, L2E, -mla);
        sskA[h] = fmaf(ssa, KA, -mla);
        float ssb = g_ssrc4[ib * 4 + h];
        float eb = ssb + M; eb = fmaxf(eb, GAT_ALPHA * eb);
        float mlb = eb * L2E;
        sslB[h] = fmaf(ssb, L2E, -mlb);
        sskB[h] = fmaf(ssb, KA, -mlb);
    }

    float zA[4], zB[4];

#pragma unroll 1
    for (int hp = 0; hp < 2; hp++) {
        __syncthreads();
#pragma unroll
        for (int q = 0; q < 2; q++) {
            int f = q * 128 + threadIdx.x;
            int j = f >> 2, cc = (f & 3) * 4;
            *(float4*)&s_wh[j * 16 + cc] =
                *(const float4*)&g_Wh[(size_t)(j0 + j) * NC32 + hp * 16 + cc];
        }
        if (threadIdx.x < 64) {
            float4 sd = ((const float4*)g_sdst4)[j0 + threadIdx.x];
            float a0 = hp ? sd.z : sd.x;
            float b0 = hp ? sd.w : sd.y;
            *(float4*)&s_sd[threadIdx.x * 4] =
                make_float4(a0 * L2E, a0 * KA, b0 * L2E, b0 * KA);
        }
        __syncthreads();

        int h0 = hp * 2;
        float sa0 = sslA[h0], ka0 = sskA[h0], sa1 = sslA[h0 + 1], ka1 = sskA[h0 + 1];
        float sb0 = sslB[h0], kb0 = sskB[h0], sb1 = sslB[h0 + 1], kb1 = sskB[h0 + 1];
        unsigned long long accA[8], accB[8], zpA = 0ull, zpB = 0ull;
#pragma unroll
        for (int m = 0; m < 8; m++) { accA[m] = 0ull; accB[m] = 0ull; }

#pragma unroll
        for (int q = 0; q < 4; q++) {
            unsigned wa = g_bmT[(size_t)(g * 4 + q) * NN + ia] >> lhalf;
            unsigned wb = g_bmT[(size_t)(g * 4 + q) * NN + ib] >> lhalf;
#pragma unroll 8
            for (int l = 0; l < 16; l++) {
                int jj = l * 4 + q;
                float4 sd = *(const float4*)&s_sd[jj * 4];
                float wt0a = ex2f(fmaxf(sd.x + sa0, sd.y + ka0));
                float wt1a = ex2f(fmaxf(sd.z + sa1, sd.w + ka1));
                float wt0b = ex2f(fmaxf(sd.x + sb0, sd.y + kb0));
                float wt1b = ex2f(fmaxf(sd.z + sb1, sd.w + kb1));
                bool oa = (wa >> l) & 1u;
                bool ob = (wb >> l) & 1u;
                wt0a = oa ? wt0a : 0.f;  wt1a = oa ? wt1a : 0.f;
                wt0b = ob ? wt0b : 0.f;  wt1b = ob ? wt1b : 0.f;
                unsigned long long wpa = packab(wt0a, wt1a);
                unsigned long long wpb = packab(wt0b, wt1b);
                addf2(zpA, wpa);
                addf2(zpB, wpb);
                const ulonglong2* wp = (const ulonglong2*)&s_wh[jj * 16];
                ulonglong2 q0 = wp[0], q1 = wp[1], q2 = wp[2], q3 = wp[3];
                ffma2(accA[0], wpa, q0.x); ffma2(accA[1], wpa, q0.y);
                ffma2(accA[2], wpa, q1.x); ffma2(accA[3], wpa, q1.y);
                ffma2(accA[4], wpa, q2.x); ffma2(accA[5], wpa, q2.y);
                ffma2(accA[6], wpa, q3.x); ffma2(accA[7], wpa, q3.y);
                ffma2(accB[0], wpb, q0.x); ffma2(accB[1], wpb, q0.y);
                ffma2(accB[2], wpb, q1.x); ffma2(accB[3], wpb, q1.y);
                ffma2(accB[4], wpb, q2.x); ffma2(accB[5], wpb, q2.y);
                ffma2(accB[6], wpb, q3.x); ffma2(accB[7], wpb, q3.y);
            }
        }
        // acc[m] = (head h0 o=m, head h0+1 o=m)
        {
            U64F2 u[8];
#pragma unroll
            for (int m = 0; m < 8; m++) u[m].u = accA[m];
            float* pa = g_hp + (size_t)ia * NC32 + h0 * 8;
            red4(pa,      u[0].f.x, u[1].f.x, u[2].f.x, u[3].f.x);
            red4(pa + 4,  u[4].f.x, u[5].f.x, u[6].f.x, u[7].f.x);
            red4(pa + 8,  u[0].f.y, u[1].f.y, u[2].f.y, u[3].f.y);
            red4(pa + 12, u[4].f.y, u[5].f.y, u[6].f.y, u[7].f.y);
#pragma unroll
            for (int m = 0; m < 8; m++) u[m].u = accB[m];
            float* pb = g_hp + (size_t)ib * NC32 + h0 * 8;
            red4(pb,      u[0].f.x, u[1].f.x, u[2].f.x, u[3].f.x);
            red4(pb + 4,  u[4].f.x, u[5].f.x, u[6].f.x, u[7].f.x);
            red4(pb + 8,  u[0].f.y, u[1].f.y, u[2].f.y, u[3].f.y);
            red4(pb + 12, u[4].f.y, u[5].f.y, u[6].f.y, u[7].f.y);
        }
        U64F2 za, zb; za.u = zpA; zb.u = zpB;
        zA[h0] = za.f.x; zA[h0 + 1] = za.f.y;
        zB[h0] = zb.f.x; zB[h0 + 1] = zb.f.y;
    }
    red4(g_z + (size_t)ia * 4, zA[0], zA[1], zA[2], zA[3]);
    red4(g_z + (size_t)ib * 4, zB[0], zB[1], zB[2], zB[3]);
}

// ---------------- 5) normalize, mean over heads, log_softmax; seed bias ----------------
__global__ void k_fin1(float* __restrict__ dne, int write_ne,
                       float* __restrict__ dout, int write_out,
                       const float* __restrict__ bl) {
    int i = blockIdx.x * 64 + threadIdx.x;    // grid 64, block 64
    if (blockIdx.x == 0 && threadIdx.x < 8 && write_out)
        dout[threadIdx.x] = __ldg(bl);        // seed bias for k_fin2 atomics
    float4 z4 = *(const float4*)&g_z[i * 4];
    float zi[4] = { 0.25f / fmaxf(z4.x, 1e-30f), 0.25f / fmaxf(z4.y, 1e-30f),
                    0.25f / fmaxf(z4.z, 1e-30f), 0.25f / fmaxf(z4.w, 1e-30f) };
    float ne[8];
#pragma unroll
    for (int o = 0; o < 8; o++) ne[o] = 0.f;
#pragma unroll
    for (int h = 0; h < 4; h++) {
        float4 p0 = *(const float4*)&g_hp[(size_t)i * NC32 + h * 8];
        float4 p1 = *(const float4*)&g_hp[(size_t)i * NC32 + h * 8 + 4];
        ne[0] = fmaf(p0.x, zi[h], ne[0]); ne[1] = fmaf(p0.y, zi[h], ne[1]);
        ne[2] = fmaf(p0.z, zi[h], ne[2]); ne[3] = fmaf(p0.w, zi[h], ne[3]);
        ne[4] = fmaf(p1.x, zi[h], ne[4]); ne[5] = fmaf(p1.y, zi[h], ne[5]);
        ne[6] = fmaf(p1.z, zi[h], ne[6]); ne[7] = fmaf(p1.w, zi[h], ne[7]);
    }
    float m = ne[0];
#pragma unroll
    for (int o = 1; o < 8; o++) m = fmaxf(m, ne[o]);
    float sum = 0.f;
#pragma unroll
    for (int o = 0; o < 8; o++) sum += expf(ne[o] - m);
    float lse = logf(sum) + m;
#pragma unroll
    for (int o = 0; o < 8; o++) g_ls[(size_t)i * NO + o] = ne[o] - lse;
    if (write_ne) {
#pragma unroll
        for (int o = 0; o < 8; o++) dne[(size_t)i * NO + o] = ne[o];
    }
}

// ---------------- 6) out = ls.T @ w_lin.T + b  (8 blocks, atomic finish) ----------------
__global__ void k_fin2(const float* __restrict__ wl, float* __restrict__ dout,
                       int write_out) {
    __shared__ float rb[256][8];
    int t = threadIdx.x;
    int i0 = blockIdx.x * 512;
    float p[8];
#pragma unroll
    for (int o = 0; o < 8; o++) p[o] = 0.f;
#pragma unroll
    for (int q = 0; q < 2; q++) {
        int i = i0 + q * 256 + t;
        float wv = __ldg(wl + i);
        float4 l0 = *(const float4*)&g_ls[(size_t)i * NO];
        float4 l1 = *(const float4*)&g_ls[(size_t)i * NO + 4];
        p[0] = fmaf(l0.x, wv, p[0]); p[1] = fmaf(l0.y, wv, p[1]);
        p[2] = fmaf(l0.z, wv, p[2]); p[3] = fmaf(l0.w, wv, p[3]);
        p[4] = fmaf(l1.x, wv, p[4]); p[5] = fmaf(l1.y, wv, p[5]);
        p[6] = fmaf(l1.z, wv, p[6]); p[7] = fmaf(l1.w, wv, p[7]);
    }
#pragma unroll
    for (int o = 0; o < 8; o++) rb[t][o] = p[o];
    __syncthreads();
    if (t < 8 && write_out) {
        float s = 0.f;
        for (int q = 0; q < 256; q++) s += rb[q][t];
        atomicAdd(&dout[t], s);
    }
}

// ---------------- launch ----------------
extern "C" void kernel_launch(void* const* d_in, const int* in_sizes, int n_in,
                              void* d_out, int out_size) {
    const float* x   = (const float*)d_in[0];
    const int*   adj = (const int*)d_in[1];
    const float* W   = (const float*)d_in[2];
    const float* a   = (const float*)d_in[3];
    const float* wl  = (const float*)d_in[4];
    const float* bl  = (const float*)d_in[5];
    float* outp = (float*)d_out;

    int write_out = 0, write_ne = 0, ne_off = 0;
    if (out_size >= 8 + NN * NO)      { write_out = 1; write_ne = 1; ne_off = 8; }
    else if (out_size == NN * NO)     { write_ne = 1; ne_off = 0; }
    else                              { write_out = 1; }

    k_pack<<<NN / 8, 256>>>(adj);
    dim3 gg(NN / 256, GKS);
    k_gemm<<<gg, 256>>>(x, W);
    k_whfin<<<NN / 32, 256>>>(a);
    dim3 ga(NN / 256, JS);
    k_attn<<<ga, 128>>>();
    k_fin1<<<NN / 64, 64>>>(outp + ne_off, write_ne, outp, write_out, bl);
    k_fin2<<<8, 256>>>(wl, outp, write_out);
}